// round 6
// baseline (speedup 1.0000x reference)
#include <cuda_runtime.h>

#define BB 32
#define TT_IN 1024
#define TP 1025
#define EMB 384
#define GC 96
#define NI4 24           // GC/4 input-channel quads
#define NWARPS 12
#define CTILE 16         // time steps per conv block
#define XROWS (CTILE + 2)

// Scratch (device globals: no allocations allowed)
__device__ int        g_cum[BB * TP];
__device__ ulonglong2 g_wt4[3 * NI4 * EMB];  // [k][i4][c]: 4 floats = w[c][4i4..4i4+3][k]

// Packed fp32x2 FMA (Blackwell): d.lo+=a.lo*b.lo ; d.hi+=a.hi*b.hi
#define FFMA2(acc, a, b) \
    asm("fma.rn.f32x2 %0, %1, %2, %0;" : "+l"(acc) : "l"(a), "l"(b))

// ---------------------------------------------------------------------------
// Merged prep: blocks [0,32) = per-batch cumsum of durations;
//              blocks >= 32  = weight pack [c][i][k] -> float4 quads [k][i4][c]
// ---------------------------------------------------------------------------
__global__ void prep_kernel(const int* __restrict__ dur,
                            const float* __restrict__ w1) {
    if (blockIdx.x < BB) {
        const int b = blockIdx.x;
        const int tid = threadIdx.x;           // 256 threads
        const int CH = 5;                      // 256*5 = 1280 >= 1025
        __shared__ int part[256];

        int base = tid * CH;
        int s = 0;
#pragma unroll
        for (int j = 0; j < CH; j++) {
            int p = base + j;
            if (p < TP) s += dur[b * TP + p];
        }
        part[tid] = s;
        __syncthreads();

        for (int off = 1; off < 256; off <<= 1) {
            int v = (tid >= off) ? part[tid - off] : 0;
            __syncthreads();
            part[tid] += v;
            __syncthreads();
        }

        int run = (tid > 0) ? part[tid - 1] : 0;
#pragma unroll
        for (int j = 0; j < CH; j++) {
            int p = base + j;
            if (p < TP) {
                run += dur[b * TP + p];
                g_cum[b * TP + p] = run;
            }
        }
    } else {
        int idx = (blockIdx.x - BB) * blockDim.x + threadIdx.x;
        if (idx >= 3 * NI4 * EMB) return;
        int c  = idx % EMB;
        int i4 = (idx / EMB) % NI4;
        int k  = idx / (EMB * NI4);
        float4 p;
        p.x = w1[c * (GC * 3) + (4 * i4 + 0) * 3 + k];
        p.y = w1[c * (GC * 3) + (4 * i4 + 1) * 3 + k];
        p.z = w1[c * (GC * 3) + (4 * i4 + 2) * 3 + k];
        p.w = w1[c * (GC * 3) + (4 * i4 + 3) * 3 + k];
        g_wt4[idx] = *(ulonglong2*)&p;
    }
}

// ---------------------------------------------------------------------------
// Fused duration predictor, f32x2-packed, 4-channel quads, CTILE=16, occ 2,
// with double-buffered weight quads (L2 latency hidden behind FFMA2 stream).
// Scatter-form inner loop: each x row position loaded exactly once (LDS.128
// broadcast), contributing to acc[lt], acc[lt-1], acc[lt-2] with w_k quads.
// ---------------------------------------------------------------------------
__global__ __launch_bounds__(384, 2)
void conv_kernel(const float* __restrict__ ph,
                 const float* __restrict__ sil,
                 const float* __restrict__ b1,
                 const float* __restrict__ w2,
                 const float* __restrict__ b2,
                 float* __restrict__ dpred) {
    __shared__ float xs[XROWS * EMB];      // [t][c]
    __shared__ float red[NWARPS * CTILE];

    const int b   = blockIdx.y;
    const int t0  = blockIdx.x * CTILE;
    const int tid = threadIdx.x;           // output channel c

    // Stage x tile [t][c]: global t = t0-1+lt; t==1024 -> silence; else zero.
#pragma unroll
    for (int lt = 0; lt < XROWS; lt++) {
        int tg = t0 - 1 + lt;
        float v = 0.f;
        if ((unsigned)tg < TT_IN)  v = ph[((size_t)b * TT_IN + tg) * EMB + tid];
        else if (tg == TT_IN)      v = sil[tid];
        xs[lt * EMB + tid] = v;
    }
    __syncthreads();

    const int cbase = (tid / GC) * GC;     // group channel base

    unsigned long long acc[CTILE];
#pragma unroll
    for (int t = 0; t < CTILE; t++) acc[t] = 0ULL;

    const ulonglong2* wq = g_wt4 + tid;

    // Weight double-buffer: next i4's quads in flight during this i4's FFMA2s.
    ulonglong2 w0  = wq[(0 * NI4 + 0) * EMB];
    ulonglong2 w1  = wq[(1 * NI4 + 0) * EMB];
    ulonglong2 w2q = wq[(2 * NI4 + 0) * EMB];

    for (int i4 = 0; i4 < NI4; i4++) {
        const int nx = (i4 + 1 < NI4) ? (i4 + 1) : i4;
        ulonglong2 n0 = wq[(0 * NI4 + nx) * EMB];
        ulonglong2 n1 = wq[(1 * NI4 + nx) * EMB];
        ulonglong2 n2 = wq[(2 * NI4 + nx) * EMB];

        const ulonglong2* xq =
            (const ulonglong2*)(xs + cbase + 4 * i4);   // row stride EMB floats
#pragma unroll
        for (int lt = 0; lt < XROWS; lt++) {
            ulonglong2 x = xq[lt * (EMB / 4)];
            if (lt < CTILE)                 { FFMA2(acc[lt],     w0.x,  x.x); FFMA2(acc[lt],     w0.y,  x.y); }
            if (lt >= 1 && lt - 1 < CTILE)  { FFMA2(acc[lt - 1], w1.x,  x.x); FFMA2(acc[lt - 1], w1.y,  x.y); }
            if (lt >= 2)                    { FFMA2(acc[lt - 2], w2q.x, x.x); FFMA2(acc[lt - 2], w2q.y, x.y); }
        }
        w0 = n0; w1 = n1; w2q = n2;
    }

    // Epilogue: lo+hi+bias, ReLU, * w2[c], reduce over 384 channels.
    const float bias = b1[tid];
    const float w2c  = w2[tid];
    const int lane = tid & 31;
    const int warp = tid >> 5;
#pragma unroll
    for (int t = 0; t < CTILE; t++) {
        unsigned lo, hi;
        asm("mov.b64 {%0,%1}, %2;" : "=r"(lo), "=r"(hi) : "l"(acc[t]));
        float v = __uint_as_float(lo) + __uint_as_float(hi) + bias;
        v = w2c * fmaxf(v, 0.f);
        v += __shfl_down_sync(0xffffffffu, v, 16);
        v += __shfl_down_sync(0xffffffffu, v, 8);
        v += __shfl_down_sync(0xffffffffu, v, 4);
        v += __shfl_down_sync(0xffffffffu, v, 2);
        v += __shfl_down_sync(0xffffffffu, v, 1);
        if (lane == 0) red[warp * CTILE + t] = v;
    }
    __syncthreads();

    if (tid < CTILE) {
        int t = t0 + tid;
        if (t < TP) {
            float s = b2[0];
#pragma unroll
            for (int w = 0; w < NWARPS; w++) s += red[w * CTILE + tid];
            dpred[b * TP + t] = s;
        }
    }
}

// ---------------------------------------------------------------------------
// Length regulation by SCATTER: one warp per (b, token j).
// ---------------------------------------------------------------------------
__global__ void scatter_kernel(const float* __restrict__ ph,
                               const float* __restrict__ sil,
                               float* __restrict__ out,
                               int t_out) {
    const int w = (blockIdx.x * blockDim.x + threadIdx.x) >> 5;
    const int lane = threadIdx.x & 31;
    if (w >= BB * TP) return;
    const int b = w / TP;
    const int j = w - b * TP;

    const int hi = g_cum[b * TP + j];
    const int lo = j ? g_cum[b * TP + j - 1] : 0;
    const int d = hi - lo;
    if (d <= 0) return;

    const float4* src = (j < TT_IN)
        ? (const float4*)(ph + ((size_t)b * TT_IN + j) * EMB)
        : (const float4*)sil;
    float4 r0 = __ldcs(src + lane);
    float4 r1 = __ldcs(src + 32 + lane);
    float4 r2 = __ldcs(src + 64 + lane);

    float4* dst = (float4*)(out + ((size_t)b * t_out + lo) * EMB);
    for (int f = 0; f < d; f++, dst += EMB / 4) {
        __stcs(dst + lane,      r0);
        __stcs(dst + 32 + lane, r1);
        __stcs(dst + 64 + lane, r2);
    }
}

// Zero-fill frames past each batch's total length (out buffer is poisoned).
__global__ void zerotail_kernel(float* __restrict__ out, int t_out) {
    const int b = blockIdx.x;
    const int tot = g_cum[b * TP + TP - 1];
    if (tot >= t_out) return;
    float4* dst = (float4*)(out + ((size_t)b * t_out + tot) * EMB);
    const int n4 = (t_out - tot) * (EMB / 4);
    const float4 z = make_float4(0.f, 0.f, 0.f, 0.f);
    for (int i = threadIdx.x; i < n4; i += blockDim.x) __stcs(dst + i, z);
}

// ---------------------------------------------------------------------------
// Launch
// ---------------------------------------------------------------------------
extern "C" void kernel_launch(void* const* d_in, const int* in_sizes, int n_in,
                              void* d_out, int out_size) {
    const float* ph  = (const float*)d_in[0];   // [32,1024,384]
    const float* sil = (const float*)d_in[1];   // [384]
    const float* w1  = (const float*)d_in[2];   // [384,96,3]
    const float* b1  = (const float*)d_in[3];   // [384]
    const float* w2  = (const float*)d_in[4];   // [1,384,1]
    const float* b2  = (const float*)d_in[5];   // [1]
    const int*   dur = (const int*)d_in[6];     // [32,1025]

    const int t_out = (out_size - BB * TP) / (BB * EMB);

    float* out_exp  = (float*)d_out;                             // [B,t_out,EMB]
    float* out_pred = (float*)d_out + (size_t)BB * t_out * EMB;  // [B,TP]

    const int wblocks = (3 * NI4 * EMB + 255) / 256;
    prep_kernel<<<BB + wblocks, 256>>>(dur, w1);

    dim3 cgrid((TP + CTILE - 1) / CTILE, BB);
    conv_kernel<<<cgrid, EMB>>>(ph, sil, b1, w2, b2, out_pred);

    const int warps = BB * TP;
    scatter_kernel<<<(warps * 32 + 255) / 256, 256>>>(ph, sil, out_exp, t_out);
    zerotail_kernel<<<BB, 256>>>(out_exp, t_out);
}

// round 7
// speedup vs baseline: 1.0756x; 1.0756x over previous
#include <cuda_runtime.h>

#define BB 32
#define TT_IN 1024
#define TP 1025
#define EMB 384
#define GC 96
#define NI4 24           // GC/4 input-channel quads
#define NWARPS 12
#define CTILE 16         // time steps per conv block
#define XROWS (CTILE + 2)
#define ZWARPS 64        // tail-zero warps per batch (inside scatter)

// Scratch (device globals: no allocations allowed)
__device__ int        g_cum[BB * TP];
__device__ ulonglong2 g_wt4[3 * NI4 * EMB];  // [k][i4][c]: 4 floats = w[c][4i4..4i4+3][k]

// Packed fp32x2 FMA (Blackwell): d.lo+=a.lo*b.lo ; d.hi+=a.hi*b.hi
#define FFMA2(acc, a, b) \
    asm("fma.rn.f32x2 %0, %1, %2, %0;" : "+l"(acc) : "l"(a), "l"(b))

// ---------------------------------------------------------------------------
// Merged prep: blocks [0,32) = per-batch cumsum of durations;
//              blocks >= 32  = weight pack [c][i][k] -> float4 quads [k][i4][c]
// ---------------------------------------------------------------------------
__global__ void prep_kernel(const int* __restrict__ dur,
                            const float* __restrict__ w1) {
    if (blockIdx.x < BB) {
        const int b = blockIdx.x;
        const int tid = threadIdx.x;           // 256 threads
        const int CH = 5;                      // 256*5 = 1280 >= 1025
        __shared__ int part[256];

        int base = tid * CH;
        int s = 0;
#pragma unroll
        for (int j = 0; j < CH; j++) {
            int p = base + j;
            if (p < TP) s += dur[b * TP + p];
        }
        part[tid] = s;
        __syncthreads();

        for (int off = 1; off < 256; off <<= 1) {
            int v = (tid >= off) ? part[tid - off] : 0;
            __syncthreads();
            part[tid] += v;
            __syncthreads();
        }

        int run = (tid > 0) ? part[tid - 1] : 0;
#pragma unroll
        for (int j = 0; j < CH; j++) {
            int p = base + j;
            if (p < TP) {
                run += dur[b * TP + p];
                g_cum[b * TP + p] = run;
            }
        }
    } else {
        int idx = (blockIdx.x - BB) * blockDim.x + threadIdx.x;
        if (idx >= 3 * NI4 * EMB) return;
        int c  = idx % EMB;
        int i4 = (idx / EMB) % NI4;
        int k  = idx / (EMB * NI4);
        float4 p;
        p.x = w1[c * (GC * 3) + (4 * i4 + 0) * 3 + k];
        p.y = w1[c * (GC * 3) + (4 * i4 + 1) * 3 + k];
        p.z = w1[c * (GC * 3) + (4 * i4 + 2) * 3 + k];
        p.w = w1[c * (GC * 3) + (4 * i4 + 3) * 3 + k];
        g_wt4[idx] = *(ulonglong2*)&p;
    }
}

// ---------------------------------------------------------------------------
// Fused duration predictor, f32x2-packed, 4-channel quads, CTILE=16, occ 2.
// (Exact R5 structure — measured best; no weight double-buffer.)
// ---------------------------------------------------------------------------
__global__ __launch_bounds__(384, 2)
void conv_kernel(const float* __restrict__ ph,
                 const float* __restrict__ sil,
                 const float* __restrict__ b1,
                 const float* __restrict__ w2,
                 const float* __restrict__ b2,
                 float* __restrict__ dpred) {
    __shared__ float xs[XROWS * EMB];      // [t][c]
    __shared__ float red[NWARPS * CTILE];

    const int b   = blockIdx.y;
    const int t0  = blockIdx.x * CTILE;
    const int tid = threadIdx.x;           // output channel c

    // Stage x tile [t][c]: global t = t0-1+lt; t==1024 -> silence; else zero.
#pragma unroll
    for (int lt = 0; lt < XROWS; lt++) {
        int tg = t0 - 1 + lt;
        float v = 0.f;
        if ((unsigned)tg < TT_IN)  v = ph[((size_t)b * TT_IN + tg) * EMB + tid];
        else if (tg == TT_IN)      v = sil[tid];
        xs[lt * EMB + tid] = v;
    }
    __syncthreads();

    const int cbase = (tid / GC) * GC;     // group channel base

    unsigned long long acc[CTILE];
#pragma unroll
    for (int t = 0; t < CTILE; t++) acc[t] = 0ULL;

    const ulonglong2* wq = g_wt4 + tid;

    for (int i4 = 0; i4 < NI4; i4++) {
        ulonglong2 w0  = wq[(0 * NI4 + i4) * EMB];
        ulonglong2 w1  = wq[(1 * NI4 + i4) * EMB];
        ulonglong2 w2q = wq[(2 * NI4 + i4) * EMB];

        const ulonglong2* xq =
            (const ulonglong2*)(xs + cbase + 4 * i4);   // row stride EMB floats
#pragma unroll
        for (int lt = 0; lt < XROWS; lt++) {
            ulonglong2 x = xq[lt * (EMB / 4)];
            if (lt < CTILE)                 { FFMA2(acc[lt],     w0.x,  x.x); FFMA2(acc[lt],     w0.y,  x.y); }
            if (lt >= 1 && lt - 1 < CTILE)  { FFMA2(acc[lt - 1], w1.x,  x.x); FFMA2(acc[lt - 1], w1.y,  x.y); }
            if (lt >= 2)                    { FFMA2(acc[lt - 2], w2q.x, x.x); FFMA2(acc[lt - 2], w2q.y, x.y); }
        }
    }

    // Epilogue: lo+hi+bias, ReLU, * w2[c], reduce over 384 channels.
    const float bias = b1[tid];
    const float w2c  = w2[tid];
    const int lane = tid & 31;
    const int warp = tid >> 5;
#pragma unroll
    for (int t = 0; t < CTILE; t++) {
        unsigned lo, hi;
        asm("mov.b64 {%0,%1}, %2;" : "=r"(lo), "=r"(hi) : "l"(acc[t]));
        float v = __uint_as_float(lo) + __uint_as_float(hi) + bias;
        v = w2c * fmaxf(v, 0.f);
        v += __shfl_down_sync(0xffffffffu, v, 16);
        v += __shfl_down_sync(0xffffffffu, v, 8);
        v += __shfl_down_sync(0xffffffffu, v, 4);
        v += __shfl_down_sync(0xffffffffu, v, 2);
        v += __shfl_down_sync(0xffffffffu, v, 1);
        if (lane == 0) red[warp * CTILE + t] = v;
    }
    __syncthreads();

    if (tid < CTILE) {
        int t = t0 + tid;
        if (t < TP) {
            float s = b2[0];
#pragma unroll
            for (int w = 0; w < NWARPS; w++) s += red[w * CTILE + tid];
            dpred[b * TP + t] = s;
        }
    }
}

// ---------------------------------------------------------------------------
// Length regulation by SCATTER + fused tail-zeroing.
// Warps [0, BB*TP): one warp per (b, token j) -> replicate row d times.
// Warps [BB*TP, BB*TP + BB*ZWARPS): zero rows past cum[last] (strided).
// ---------------------------------------------------------------------------
__global__ void scatter_kernel(const float* __restrict__ ph,
                               const float* __restrict__ sil,
                               float* __restrict__ out,
                               int t_out) {
    const int w = (blockIdx.x * blockDim.x + threadIdx.x) >> 5;
    const int lane = threadIdx.x & 31;

    if (w < BB * TP) {
        const int b = w / TP;
        const int j = w - b * TP;

        const int hi = g_cum[b * TP + j];
        const int lo = j ? g_cum[b * TP + j - 1] : 0;
        const int d = hi - lo;
        if (d <= 0) return;

        const float4* src = (j < TT_IN)
            ? (const float4*)(ph + ((size_t)b * TT_IN + j) * EMB)
            : (const float4*)sil;
        float4 r0 = __ldcs(src + lane);
        float4 r1 = __ldcs(src + 32 + lane);
        float4 r2 = __ldcs(src + 64 + lane);

        float4* dst = (float4*)(out + ((size_t)b * t_out + lo) * EMB);
        for (int f = 0; f < d; f++, dst += EMB / 4) {
            __stcs(dst + lane,      r0);
            __stcs(dst + 32 + lane, r1);
            __stcs(dst + 64 + lane, r2);
        }
    } else {
        const int zw = w - BB * TP;
        if (zw >= BB * ZWARPS) return;
        const int b  = zw / ZWARPS;
        const int zi = zw - b * ZWARPS;
        const int tot = g_cum[b * TP + TP - 1];
        const float4 z = make_float4(0.f, 0.f, 0.f, 0.f);
        for (int t = tot + zi; t < t_out; t += ZWARPS) {
            float4* dst = (float4*)(out + ((size_t)b * t_out + t) * EMB);
            __stcs(dst + lane,      z);
            __stcs(dst + 32 + lane, z);
            __stcs(dst + 64 + lane, z);
        }
    }
}

// ---------------------------------------------------------------------------
// Launch
// ---------------------------------------------------------------------------
extern "C" void kernel_launch(void* const* d_in, const int* in_sizes, int n_in,
                              void* d_out, int out_size) {
    const float* ph  = (const float*)d_in[0];   // [32,1024,384]
    const float* sil = (const float*)d_in[1];   // [384]
    const float* w1  = (const float*)d_in[2];   // [384,96,3]
    const float* b1  = (const float*)d_in[3];   // [384]
    const float* w2  = (const float*)d_in[4];   // [1,384,1]
    const float* b2  = (const float*)d_in[5];   // [1]
    const int*   dur = (const int*)d_in[6];     // [32,1025]

    const int t_out = (out_size - BB * TP) / (BB * EMB);

    float* out_exp  = (float*)d_out;                             // [B,t_out,EMB]
    float* out_pred = (float*)d_out + (size_t)BB * t_out * EMB;  // [B,TP]

    const int wblocks = (3 * NI4 * EMB + 255) / 256;
    prep_kernel<<<BB + wblocks, 256>>>(dur, w1);

    dim3 cgrid((TP + CTILE - 1) / CTILE, BB);
    conv_kernel<<<cgrid, EMB>>>(ph, sil, b1, w2, b2, out_pred);

    const int warps = BB * TP + BB * ZWARPS;
    scatter_kernel<<<(warps * 32 + 255) / 256, 256>>>(ph, sil, out_exp, t_out);
}

// round 8
// speedup vs baseline: 1.4085x; 1.3095x over previous
#include <cuda_runtime.h>

#define BB 32
#define TT_IN 1024
#define TP 1025
#define EMB 384
#define GC 96
#define NWARPS 12
#define NKS 36            // K-steps per group: 3 taps * 96 ch / 8
#define NCHUNK 10
#define SUBS 7            // m16-subtiles per chunk (10*7*16 = 1120 >= 1025)
#define XS_PAD 100        // padded row stride (words) -> conflict-free frags
#define ZWARPS 64         // tail-zero warps per batch (inside scatter)
#define PWARPS ((BB * TP + 31) / 32)   // pred-sum warps inside scatter

// Scratch (device globals: no allocations allowed)
__device__ int          g_cum[BB * TP];
__device__ unsigned int g_wB[4 * NWARPS * NKS * 2 * 32];  // tf32 B fragments
__device__ float        g_part[4 * BB * TP];              // per-group pred partials

#define CVT_TF32(u, f) asm("cvt.rna.tf32.f32 %0, %1;" : "=r"(u) : "f"(f))

#define MMA_TF32(d0,d1,d2,d3, a0,a1,a2,a3, b0,b1)                          \
    asm("mma.sync.aligned.m16n8k8.row.col.f32.tf32.tf32.f32 "              \
        "{%0,%1,%2,%3}, {%4,%5,%6,%7}, {%8,%9}, {%0,%1,%2,%3};"            \
        : "+f"(d0), "+f"(d1), "+f"(d2), "+f"(d3)                           \
        : "r"(a0), "r"(a1), "r"(a2), "r"(a3), "r"(b0), "r"(b1))

// ---------------------------------------------------------------------------
// Merged prep: blocks [0,32) = per-batch cumsum; blocks >= 32 = pack conv1
// weights into tf32 mma B-fragment order (validated in R4):
// g_wB[g][nt][ks][r][lane]; b_r = W[k = (ks%12)*8 + (lane&3) + 4r][n], tap kk=ks/12,
// n = nt*8 + lane/4.
// ---------------------------------------------------------------------------
__global__ void prep_kernel(const int* __restrict__ dur,
                            const float* __restrict__ w1) {
    if (blockIdx.x < BB) {
        const int b = blockIdx.x;
        const int tid = threadIdx.x;           // 256 threads
        const int CH = 5;                      // 256*5 = 1280 >= 1025
        __shared__ int part[256];

        int base = tid * CH;
        int s = 0;
#pragma unroll
        for (int j = 0; j < CH; j++) {
            int p = base + j;
            if (p < TP) s += dur[b * TP + p];
        }
        part[tid] = s;
        __syncthreads();

        for (int off = 1; off < 256; off <<= 1) {
            int v = (tid >= off) ? part[tid - off] : 0;
            __syncthreads();
            part[tid] += v;
            __syncthreads();
        }

        int run = (tid > 0) ? part[tid - 1] : 0;
#pragma unroll
        for (int j = 0; j < CH; j++) {
            int p = base + j;
            if (p < TP) {
                run += dur[b * TP + p];
                g_cum[b * TP + p] = run;
            }
        }
    } else {
        int t = (blockIdx.x - BB) * blockDim.x + threadIdx.x;
        if (t >= 4 * NWARPS * NKS * 32) return;
        int lane = t & 31;
        int rest = t >> 5;
        int ks = rest % NKS;
        int nt = (rest / NKS) % NWARPS;
        int g  = rest / (NKS * NWARPS);

        int kk = ks / 12;
        int n  = nt * 8 + (lane >> 2);
        int C  = g * GC + n;
#pragma unroll
        for (int r = 0; r < 2; r++) {
            int i = (ks % 12) * 8 + (lane & 3) + 4 * r;
            float w = w1[C * (GC * 3) + i * 3 + kk];
            unsigned u; CVT_TF32(u, w);
            g_wB[(((g * NWARPS + nt) * NKS + ks) * 2 + r) * 32 + lane] = u;
        }
    }
}

// ---------------------------------------------------------------------------
// tf32 tensor-core duration predictor (restructured R4).
// grid = (BB, 4 groups, NCHUNK); block = 384 = 12 warps (warp = n-tile of 8).
// Double-buffered x staging + 2 interleaved K-chains per accumulator.
// ---------------------------------------------------------------------------
__global__ __launch_bounds__(384)
void conv_mma_kernel(const float* __restrict__ ph,
                     const float* __restrict__ sil,
                     const float* __restrict__ b1,
                     const float* __restrict__ w2) {
    __shared__ unsigned int xs[2][18 * XS_PAD];
    __shared__ float red[16 * NWARPS];

    const int b     = blockIdx.x;
    const int g     = blockIdx.y;
    const int chunk = blockIdx.z;
    const int tbase = chunk * (SUBS * 16);
    const int tid   = threadIdx.x;
    const int wid   = tid >> 5;       // n-tile
    const int lane  = tid & 31;
    const int g4    = lane >> 2;      // row within fragment
    const int t4    = lane & 3;       // col within fragment

    // B fragments (72 regs), once per block. (Validated R4.)
    unsigned int Breg0[NKS], Breg1[NKS];
    {
        const unsigned int* wb =
            g_wB + ((g * NWARPS + wid) * NKS) * 2 * 32 + lane;
#pragma unroll
        for (int ks = 0; ks < NKS; ks++) {
            Breg0[ks] = wb[(ks * 2 + 0) * 32];
            Breg1[ks] = wb[(ks * 2 + 1) * 32];
        }
    }

    const int c0 = wid * 8 + 2 * t4;
    const int C0 = g * GC + c0;
    const float w2_0 = w2[C0],     w2_1 = w2[C0 + 1];
    const float b1_0 = b1[C0],     b1_1 = b1[C0 + 1];

    // Prologue: stage subtile 0 into buffer 0.
    {
        const int ts0 = tbase;
#pragma unroll
        for (int i = 0; i < 5; i++) {
            int e = tid + i * 384;
            if (e < 18 * GC) {
                int row = e / GC, col = e - row * GC;
                int tg = ts0 - 1 + row;
                float v = 0.f;
                if ((unsigned)tg < TT_IN) v = ph[((size_t)b * TT_IN + tg) * EMB + g * GC + col];
                else if (tg == TT_IN)     v = sil[g * GC + col];
                unsigned u; CVT_TF32(u, v);
                xs[0][row * XS_PAD + col] = u;
            }
        }
    }
    __syncthreads();

    for (int sub = 0; sub < SUBS; sub++) {
        const int tsub0 = tbase + sub * 16;
        if (tsub0 >= TP) break;              // block-uniform
        const int cur = sub & 1;
        const bool have_next = (sub + 1 < SUBS) && (tbase + (sub + 1) * 16 < TP);

        // Prefetch next subtile's x into registers (overlaps with MMA issue).
        float xv[5];
        if (have_next) {
            const int ts1 = tsub0 + 16;
#pragma unroll
            for (int i = 0; i < 5; i++) {
                int e = tid + i * 384;
                float v = 0.f;
                if (e < 18 * GC) {
                    int row = e / GC, col = e - row * GC;
                    int tg = ts1 - 1 + row;
                    if ((unsigned)tg < TT_IN) v = ph[((size_t)b * TT_IN + tg) * EMB + g * GC + col];
                    else if (tg == TT_IN)     v = sil[g * GC + col];
                }
                xv[i] = v;
            }
        }

        // MMA on current buffer: 2 interleaved K-chains (independent HMMA streams).
        float dA0 = 0.f, dA1 = 0.f, dA2 = 0.f, dA3 = 0.f;
        float dB0 = 0.f, dB1 = 0.f, dB2 = 0.f, dB3 = 0.f;
#pragma unroll
        for (int kk = 0; kk < 3; kk++) {
            const unsigned int* xrow  = xs[cur] + (g4 + kk) * XS_PAD + t4;
            const unsigned int* xrow8 = xrow + 8 * XS_PAD;
#pragma unroll
            for (int ki = 0; ki < 12; ki++) {
                const int ib = ki * 8;
                unsigned a0 = xrow[ib];
                unsigned a1 = xrow8[ib];
                unsigned a2 = xrow[ib + 4];
                unsigned a3 = xrow8[ib + 4];
                const int ks = kk * 12 + ki;
                if (ki & 1) { MMA_TF32(dB0, dB1, dB2, dB3, a0, a1, a2, a3, Breg0[ks], Breg1[ks]); }
                else        { MMA_TF32(dA0, dA1, dA2, dA3, a0, a1, a2, a3, Breg0[ks], Breg1[ks]); }
            }
        }
        float d0 = dA0 + dB0, d1 = dA1 + dB1, d2 = dA2 + dB2, d3 = dA3 + dB3;

        // Commit the prefetched tile to the other buffer.
        if (have_next) {
#pragma unroll
            for (int i = 0; i < 5; i++) {
                int e = tid + i * 384;
                if (e < 18 * GC) {
                    int row = e / GC, col = e - row * GC;
                    unsigned u; CVT_TF32(u, xv[i]);
                    xs[cur ^ 1][row * XS_PAD + col] = u;
                }
            }
        }

        // Epilogue: relu + b1, dot w2 for this thread's 2 channels, 2 rows.
        float pl  = w2_0 * fmaxf(d0 + b1_0, 0.f) + w2_1 * fmaxf(d1 + b1_1, 0.f);
        float ph_ = w2_0 * fmaxf(d2 + b1_0, 0.f) + w2_1 * fmaxf(d3 + b1_1, 0.f);
        pl  += __shfl_xor_sync(0xffffffffu, pl, 1);
        pl  += __shfl_xor_sync(0xffffffffu, pl, 2);
        ph_ += __shfl_xor_sync(0xffffffffu, ph_, 1);
        ph_ += __shfl_xor_sync(0xffffffffu, ph_, 2);
        if (t4 == 0) {
            red[g4 * NWARPS + wid]       = pl;
            red[(g4 + 8) * NWARPS + wid] = ph_;
        }
        __syncthreads();

        if (tid < 16) {
            int t = tsub0 + tid;
            if (t < TP) {
                float s = 0.f;
#pragma unroll
                for (int w = 0; w < NWARPS; w++) s += red[tid * NWARPS + w];
                g_part[(g * BB + b) * TP + t] = s;
            }
        }
        __syncthreads();   // red consumed; xs[nxt] stores visible
    }
}

// ---------------------------------------------------------------------------
// SCATTER + tail-zero + pred-sum, one kernel.
// Warps [0, BB*TP): replicate token row d times.
// Warps [BB*TP, +BB*ZWARPS): zero rows past cum[last].
// Warps [BB*TP+BB*ZWARPS, +PWARPS): sum 4 group partials + b2 -> dpred.
// ---------------------------------------------------------------------------
__global__ void scatter_kernel(const float* __restrict__ ph,
                               const float* __restrict__ sil,
                               const float* __restrict__ b2,
                               float* __restrict__ out,
                               float* __restrict__ dpred,
                               int t_out) {
    const int w = (blockIdx.x * blockDim.x + threadIdx.x) >> 5;
    const int lane = threadIdx.x & 31;

    if (w < BB * TP) {
        const int b = w / TP;
        const int j = w - b * TP;

        const int hi = g_cum[b * TP + j];
        const int lo = j ? g_cum[b * TP + j - 1] : 0;
        const int d = hi - lo;
        if (d <= 0) return;

        const float4* src = (j < TT_IN)
            ? (const float4*)(ph + ((size_t)b * TT_IN + j) * EMB)
            : (const float4*)sil;
        float4 r0 = __ldcs(src + lane);
        float4 r1 = __ldcs(src + 32 + lane);
        float4 r2 = __ldcs(src + 64 + lane);

        float4* dst = (float4*)(out + ((size_t)b * t_out + lo) * EMB);
        for (int f = 0; f < d; f++, dst += EMB / 4) {
            __stcs(dst + lane,      r0);
            __stcs(dst + 32 + lane, r1);
            __stcs(dst + 64 + lane, r2);
        }
    } else if (w < BB * TP + BB * ZWARPS) {
        const int zw = w - BB * TP;
        const int b  = zw / ZWARPS;
        const int zi = zw - b * ZWARPS;
        const int tot = g_cum[b * TP + TP - 1];
        const float4 z = make_float4(0.f, 0.f, 0.f, 0.f);
        for (int t = tot + zi; t < t_out; t += ZWARPS) {
            float4* dst = (float4*)(out + ((size_t)b * t_out + t) * EMB);
            __stcs(dst + lane,      z);
            __stcs(dst + 32 + lane, z);
            __stcs(dst + 64 + lane, z);
        }
    } else {
        const int pw = w - BB * TP - BB * ZWARPS;
        if (pw >= PWARPS) return;
        const int i = pw * 32 + lane;
        if (i >= BB * TP) return;
        float s = b2[0];
#pragma unroll
        for (int g = 0; g < 4; g++) s += g_part[g * BB * TP + i];
        dpred[i] = s;
    }
}

// ---------------------------------------------------------------------------
// Launch
// ---------------------------------------------------------------------------
extern "C" void kernel_launch(void* const* d_in, const int* in_sizes, int n_in,
                              void* d_out, int out_size) {
    const float* ph  = (const float*)d_in[0];   // [32,1024,384]
    const float* sil = (const float*)d_in[1];   // [384]
    const float* w1  = (const float*)d_in[2];   // [384,96,3]
    const float* b1  = (const float*)d_in[3];   // [384]
    const float* w2  = (const float*)d_in[4];   // [1,384,1]
    const float* b2  = (const float*)d_in[5];   // [1]
    const int*   dur = (const int*)d_in[6];     // [32,1025]

    const int t_out = (out_size - BB * TP) / (BB * EMB);

    float* out_exp  = (float*)d_out;                             // [B,t_out,EMB]
    float* out_pred = (float*)d_out + (size_t)BB * t_out * EMB;  // [B,TP]

    const int wblocks = (4 * NWARPS * NKS * 32 + 255) / 256;
    prep_kernel<<<BB + wblocks, 256>>>(dur, w1);

    dim3 cgrid(BB, 4, NCHUNK);
    conv_mma_kernel<<<cgrid, 384>>>(ph, sil, b1, w2);

    const int warps = BB * TP + BB * ZWARPS + PWARPS;
    scatter_kernel<<<(warps * 32 + 255) / 256, 256>>>(ph, sil, b2,
                                                      out_exp, out_pred, t_out);
}

// round 9
// speedup vs baseline: 1.5337x; 1.0889x over previous
#include <cuda_runtime.h>

#define BB 32
#define TT_IN 1024
#define TP 1025
#define EMB 384
#define GC 96
#define NWARPS 12
#define NKS 36            // total K-steps: 3 taps * 96 ch / 8
#define NCHUNK 10
#define SUBS 7            // m16-subtiles per chunk (10*7*16 = 1120 >= 1025)
#define ZWARPS 64         // tail-zero warps per batch (inside scatter)
#define PWARPS ((BB * TP + 31) / 32)   // pred-sum warps inside scatter
#define NPART 16          // 4 groups * 4 n-groups partials

// Scratch (device globals: no allocations allowed)
__device__ int          g_cum[BB * TP];
__device__ unsigned int g_wB[4 * NWARPS * NKS * 2 * 32];  // tf32 B fragments
__device__ float        g_part[NPART * BB * TP];          // pred partials

#define CVT_TF32(u, f) asm("cvt.rna.tf32.f32 %0, %1;" : "=r"(u) : "f"(f))

#define MMA_TF32(d0,d1,d2,d3, a0,a1,a2,a3, b0,b1)                          \
    asm("mma.sync.aligned.m16n8k8.row.col.f32.tf32.tf32.f32 "              \
        "{%0,%1,%2,%3}, {%4,%5,%6,%7}, {%8,%9}, {%0,%1,%2,%3};"            \
        : "+f"(d0), "+f"(d1), "+f"(d2), "+f"(d3)                           \
        : "r"(a0), "r"(a1), "r"(a2), "r"(a3), "r"(b0), "r"(b1))

// ---------------------------------------------------------------------------
// Merged prep: blocks [0,32) = per-batch cumsum; blocks >= 32 = pack conv1
// weights into tf32 mma B-fragment order (validated R4/R8).
// ---------------------------------------------------------------------------
__global__ void prep_kernel(const int* __restrict__ dur,
                            const float* __restrict__ w1) {
    if (blockIdx.x < BB) {
        const int b = blockIdx.x;
        const int tid = threadIdx.x;           // 256 threads
        const int CH = 5;
        __shared__ int part[256];

        int base = tid * CH;
        int s = 0;
#pragma unroll
        for (int j = 0; j < CH; j++) {
            int p = base + j;
            if (p < TP) s += dur[b * TP + p];
        }
        part[tid] = s;
        __syncthreads();

        for (int off = 1; off < 256; off <<= 1) {
            int v = (tid >= off) ? part[tid - off] : 0;
            __syncthreads();
            part[tid] += v;
            __syncthreads();
        }

        int run = (tid > 0) ? part[tid - 1] : 0;
#pragma unroll
        for (int j = 0; j < CH; j++) {
            int p = base + j;
            if (p < TP) {
                run += dur[b * TP + p];
                g_cum[b * TP + p] = run;
            }
        }
    } else {
        int t = (blockIdx.x - BB) * blockDim.x + threadIdx.x;
        if (t >= 4 * NWARPS * NKS * 32) return;
        int lane = t & 31;
        int rest = t >> 5;
        int ks = rest % NKS;
        int nt = (rest / NKS) % NWARPS;
        int g  = rest / (NKS * NWARPS);

        int kk = ks / 12;
        int n  = nt * 8 + (lane >> 2);
        int C  = g * GC + n;
#pragma unroll
        for (int r = 0; r < 2; r++) {
            int i = (ks % 12) * 8 + (lane & 3) + 4 * r;
            float w = w1[C * (GC * 3) + i * 3 + kk];
            unsigned u; CVT_TF32(u, w);
            g_wB[(((g * NWARPS + nt) * NKS + ks) * 2 + r) * 32 + lane] = u;
        }
    }
}

// ---------------------------------------------------------------------------
// tf32 tensor-core duration predictor, k-split to cut smem traffic.
// grid = (BB, 4 groups, NCHUNK); block = 384 = 12 warps.
// Warp (ng = wid&3, kt = wid>>2): n-tiles {3ng..3ng+2}, conv tap kt.
// A staged in pair-permuted layout U[row][t4][ki] (ull, row stride 50):
//   U = { x[row][ki*8+t4], x[row][ki*8+t4+4] }  -> LDS.128 = A-frag for 2 ki.
// Pre-ReLU k-partials combined via SMEM P, epilogue in warps 0..3.
// ---------------------------------------------------------------------------
__global__ __launch_bounds__(384)
void conv_mma_kernel(const float* __restrict__ ph,
                     const float* __restrict__ sil,
                     const float* __restrict__ b1,
                     const float* __restrict__ w2) {
    __shared__ unsigned int xsbuf[2][18 * 50 * 2];   // 2 x 7.2 KB
    __shared__ float4 P[NWARPS][32][3];              // 18 KB k-partials

    const int b     = blockIdx.x;
    const int g     = blockIdx.y;
    const int chunk = blockIdx.z;
    const int tbase = chunk * (SUBS * 16);
    const int tid   = threadIdx.x;
    const int wid   = tid >> 5;
    const int lane  = tid & 31;
    const int g4    = lane >> 2;
    const int t4    = lane & 3;
    const int ng    = wid & 3;        // n-group (3 n-tiles = 24 channels)
    const int kt    = wid >> 2;       // k-third = conv tap (0..2)

    // B fragments for this warp's 3 n-tiles x 12 K-steps (72 regs).
    unsigned int Breg0[12][3], Breg1[12][3];
#pragma unroll
    for (int j = 0; j < 3; j++) {
        const int nt = ng * 3 + j;
        const unsigned int* wb = g_wB + ((g * NWARPS + nt) * NKS) * 2 * 32 + lane;
#pragma unroll
        for (int ksl = 0; ksl < 12; ksl++) {
            const int ks = kt * 12 + ksl;
            Breg0[ksl][j] = wb[(ks * 2 + 0) * 32];
            Breg1[ksl][j] = wb[(ks * 2 + 1) * 32];
        }
    }

    // Epilogue constants (readback warps 0..3 only).
    float w2v[3][2], b1v[3][2];
    if (wid < 4) {
#pragma unroll
        for (int j = 0; j < 3; j++) {
#pragma unroll
            for (int h = 0; h < 2; h++) {
                int C = g * GC + (wid * 3 + j) * 8 + t4 * 2 + h;
                w2v[j][h] = w2[C];
                b1v[j][h] = b1[C];
            }
        }
    }

    // ---- staging address helper (permuted pair layout) ----
    // element e = row*96 + col; word = (row*50 + (col&3... see below)
    // Prologue: stage subtile 0 into buffer 0 (all 384 threads, STS.32).
    {
        const int ts0 = tbase;
#pragma unroll
        for (int i = 0; i < 5; i++) {
            int e = tid + i * 384;
            if (e < 18 * GC) {
                int row = e / GC, col = e - row * GC;
                int tg = ts0 - 1 + row;
                float v = 0.f;
                if ((unsigned)tg < TT_IN) v = ph[((size_t)b * TT_IN + tg) * EMB + g * GC + col];
                else if (tg == TT_IN)     v = sil[g * GC + col];
                unsigned u; CVT_TF32(u, v);
                int ki = col >> 3, rem = col & 7;
                xsbuf[0][(row * 50 + (rem & 3) * 12 + ki) * 2 + (rem >> 2)] = u;
            }
        }
    }
    __syncthreads();

    for (int sub = 0; sub < SUBS; sub++) {
        const int tsub0 = tbase + sub * 16;
        if (tsub0 >= TP) break;              // block-uniform
        const int cur = sub & 1;
        const bool have_next = (sub + 1 < SUBS) && (tbase + (sub + 1) * 16 < TP);

        // Prefetch next subtile's x into registers (warps 4..11; 256 threads).
        float xv[7];
        if (have_next && wid >= 4) {
            const int ts1 = tsub0 + 16;
#pragma unroll
            for (int i = 0; i < 7; i++) {
                int e = (tid - 128) + i * 256;
                float v = 0.f;
                if (e < 18 * GC) {
                    int row = e / GC, col = e - row * GC;
                    int tg = ts1 - 1 + row;
                    if ((unsigned)tg < TT_IN) v = ph[((size_t)b * TT_IN + tg) * EMB + g * GC + col];
                    else if (tg == TT_IN)     v = sil[g * GC + col];
                }
                xv[i] = v;
            }
        }

        // MMA: rows (g4+kt, g4+8+kt), 12 K-steps via 6 LDS.128 pairs.
        float acc[3][4];
#pragma unroll
        for (int j = 0; j < 3; j++)
#pragma unroll
            for (int q = 0; q < 4; q++) acc[j][q] = 0.f;

        {
            const uint4* U = (const uint4*)xsbuf[cur];
            const int i0 = (g4 + kt) * 25 + t4 * 6;   // uint4 index
            const int i1 = i0 + 8 * 25;
#pragma unroll
            for (int p = 0; p < 6; p++) {
                uint4 A0 = U[i0 + p];   // {a0,a2}@2p , {a0,a2}@2p+1
                uint4 A1 = U[i1 + p];   // {a1,a3}@2p , {a1,a3}@2p+1
#pragma unroll
                for (int j = 0; j < 3; j++)
                    MMA_TF32(acc[j][0], acc[j][1], acc[j][2], acc[j][3],
                             A0.x, A1.x, A0.y, A1.y,
                             Breg0[2 * p][j], Breg1[2 * p][j]);
#pragma unroll
                for (int j = 0; j < 3; j++)
                    MMA_TF32(acc[j][0], acc[j][1], acc[j][2], acc[j][3],
                             A0.z, A1.z, A0.w, A1.w,
                             Breg0[2 * p + 1][j], Breg1[2 * p + 1][j]);
            }
        }

        // Publish pre-ReLU k-partials.
#pragma unroll
        for (int j = 0; j < 3; j++)
            P[wid][lane][j] = make_float4(acc[j][0], acc[j][1], acc[j][2], acc[j][3]);
        __syncthreads();   // P complete; xs[cur] reads done

        if (wid < 4) {
            // Combine 3 taps, ReLU + bias, dot w2, reduce, write partial.
            float vlo = 0.f, vhi = 0.f;
#pragma unroll
            for (int j = 0; j < 3; j++) {
                float4 p0 = P[wid][lane][j];
                float4 p1 = P[4 + wid][lane][j];
                float4 p2 = P[8 + wid][lane][j];
                float sx = p0.x + p1.x + p2.x;
                float sy = p0.y + p1.y + p2.y;
                float sz = p0.z + p1.z + p2.z;
                float sw = p0.w + p1.w + p2.w;
                vlo += w2v[j][0] * fmaxf(sx + b1v[j][0], 0.f)
                     + w2v[j][1] * fmaxf(sy + b1v[j][1], 0.f);
                vhi += w2v[j][0] * fmaxf(sz + b1v[j][0], 0.f)
                     + w2v[j][1] * fmaxf(sw + b1v[j][1], 0.f);
            }
            vlo += __shfl_xor_sync(0xffffffffu, vlo, 1);
            vlo += __shfl_xor_sync(0xffffffffu, vlo, 2);
            vhi += __shfl_xor_sync(0xffffffffu, vhi, 1);
            vhi += __shfl_xor_sync(0xffffffffu, vhi, 2);
            if (t4 == 0) {
                const size_t base = ((size_t)(g * 4 + wid) * BB + b) * TP;
                int t = tsub0 + g4;
                if (t < TP)     g_part[base + t] = vlo;
                if (t + 8 < TP) g_part[base + t + 8] = vhi;
            }
        } else if (have_next) {
            // Commit prefetched tile to the other buffer (permuted STS).
            const int nxt = cur ^ 1;
#pragma unroll
            for (int i = 0; i < 7; i++) {
                int e = (tid - 128) + i * 256;
                if (e < 18 * GC) {
                    int row = e / GC, col = e - row * GC;
                    unsigned u; CVT_TF32(u, xv[i]);
                    int ki = col >> 3, rem = col & 7;
                    xsbuf[nxt][(row * 50 + (rem & 3) * 12 + ki) * 2 + (rem >> 2)] = u;
                }
            }
        }
        __syncthreads();   // xs[nxt] visible; P free for reuse
    }
}

// ---------------------------------------------------------------------------
// SCATTER + tail-zero + pred-sum, one kernel.
// ---------------------------------------------------------------------------
__global__ void scatter_kernel(const float* __restrict__ ph,
                               const float* __restrict__ sil,
                               const float* __restrict__ b2,
                               float* __restrict__ out,
                               float* __restrict__ dpred,
                               int t_out) {
    const int w = (blockIdx.x * blockDim.x + threadIdx.x) >> 5;
    const int lane = threadIdx.x & 31;

    if (w < BB * TP) {
        const int b = w / TP;
        const int j = w - b * TP;

        const int hi = g_cum[b * TP + j];
        const int lo = j ? g_cum[b * TP + j - 1] : 0;
        const int d = hi - lo;
        if (d <= 0) return;

        const float4* src = (j < TT_IN)
            ? (const float4*)(ph + ((size_t)b * TT_IN + j) * EMB)
            : (const float4*)sil;
        float4 r0 = __ldcs(src + lane);
        float4 r1 = __ldcs(src + 32 + lane);
        float4 r2 = __ldcs(src + 64 + lane);

        float4* dst = (float4*)(out + ((size_t)b * t_out + lo) * EMB);
        for (int f = 0; f < d; f++, dst += EMB / 4) {
            __stcs(dst + lane,      r0);
            __stcs(dst + 32 + lane, r1);
            __stcs(dst + 64 + lane, r2);
        }
    } else if (w < BB * TP + BB * ZWARPS) {
        const int zw = w - BB * TP;
        const int b  = zw / ZWARPS;
        const int zi = zw - b * ZWARPS;
        const int tot = g_cum[b * TP + TP - 1];
        const float4 z = make_float4(0.f, 0.f, 0.f, 0.f);
        for (int t = tot + zi; t < t_out; t += ZWARPS) {
            float4* dst = (float4*)(out + ((size_t)b * t_out + t) * EMB);
            __stcs(dst + lane,      z);
            __stcs(dst + 32 + lane, z);
            __stcs(dst + 64 + lane, z);
        }
    } else {
        const int pw = w - BB * TP - BB * ZWARPS;
        if (pw >= PWARPS) return;
        const int i = pw * 32 + lane;
        if (i >= BB * TP) return;
        float s = b2[0];
#pragma unroll
        for (int q = 0; q < NPART; q++) s += g_part[(size_t)q * BB * TP + i];
        dpred[i] = s;
    }
}

// ---------------------------------------------------------------------------
// Launch
// ---------------------------------------------------------------------------
extern "C" void kernel_launch(void* const* d_in, const int* in_sizes, int n_in,
                              void* d_out, int out_size) {
    const float* ph  = (const float*)d_in[0];   // [32,1024,384]
    const float* sil = (const float*)d_in[1];   // [384]
    const float* w1  = (const float*)d_in[2];   // [384,96,3]
    const float* b1  = (const float*)d_in[3];   // [384]
    const float* w2  = (const float*)d_in[4];   // [1,384,1]
    const float* b2  = (const float*)d_in[5];   // [1]
    const int*   dur = (const int*)d_in[6];     // [32,1025]

    const int t_out = (out_size - BB * TP) / (BB * EMB);

    float* out_exp  = (float*)d_out;                             // [B,t_out,EMB]
    float* out_pred = (float*)d_out + (size_t)BB * t_out * EMB;  // [B,TP]

    const int wblocks = (4 * NWARPS * NKS * 32 + 255) / 256;
    prep_kernel<<<BB + wblocks, 256>>>(dur, w1);

    dim3 cgrid(BB, 4, NCHUNK);
    conv_mma_kernel<<<cgrid, 384>>>(ph, sil, b1, w2);

    const int warps = BB * TP + BB * ZWARPS + PWARPS;
    scatter_kernel<<<(warps * 32 + 255) / 256, 256>>>(ph, sil, b2,
                                                      out_exp, out_pred, t_out);
}